// round 1
// baseline (speedup 1.0000x reference)
#include <cuda_runtime.h>
#include <stdint.h>

// Problem constants (from reference)
#define BATCH 256
#define BH 19
#define BW 19
#define HW 361                    // 19*19
#define MAX_MOVES 3610            // HW * 10
#define BSTRIDE (MAX_MOVES * HW)  // 1,303,210 bytes per batch of history
#define HIST_TOTAL ((long long)BATCH * BSTRIDE)  // 333,621,760

// Output layout (float32, concatenated in reference return order)
#define OUT_BOARD  0
#define OUT_HIST   (BATCH * HW)                       // 92,416
#define OUT_KO     (OUT_HIST + BATCH * (long long)BSTRIDE)   // 333,714,176
#define OUT_PASS   (OUT_KO + BATCH * 2)
#define OUT_MV     (OUT_PASS + BATCH)
#define OUT_PLAYER (OUT_MV + BATCH)

// number of 16-byte chunks over the history tensor (exact: HIST_TOTAL % 16 == 0)
#define NCHUNK (333621760u / 16u)   // 20,851,360

__device__ __forceinline__ float board_state_val(float bf) {
    // where(board==0, 0, where(board==1, 1, -1))
    return (bf == 0.0f) ? 0.0f : ((bf == 1.0f) ? 1.0f : -1.0f);
}

// ---------------------------------------------------------------------------
// Kernel A: history copy int8 -> float32, with one row per batch replaced by
// the (old) board state.  This is ~1.67 GB of traffic and dominates runtime.
// ---------------------------------------------------------------------------
__global__ void __launch_bounds__(256)
hist_copy_kernel(const int8_t* __restrict__ hist,
                 const float* __restrict__ board,
                 const int* __restrict__ move_count,
                 float* __restrict__ out)
{
    unsigned int i = blockIdx.x * blockDim.x + threadIdx.x;
    if (i >= NCHUNK) return;
    unsigned int g = i * 16u;                 // global byte offset into history

    unsigned int b0   = g / (unsigned)BSTRIDE;          // const-div -> mulhi
    unsigned int off0 = g - b0 * (unsigned)BSTRIDE;     // offset within batch

    int mv    = move_count[b0];
    int valid = (mv < MAX_MOVES);
    int mvc   = mv < 0 ? 0 : (mv > MAX_MOVES - 1 ? MAX_MOVES - 1 : mv);
    unsigned int row_lo = (unsigned)mvc * HW;           // overwrite range [row_lo, row_lo+HW)

    bool cross_batch = (off0 + 16u > (unsigned)BSTRIDE);
    bool overlap = valid && (off0 < row_lo + HW) && (off0 + 16u > row_lo);

    float* __restrict__ dst = out + OUT_HIST + g;

    if (!cross_batch && !overlap) {
        // ---- fast vector path: 16 int8 -> 16 float ----
        int4 v = *reinterpret_cast<const int4*>(hist + g);
        float4 f0, f1, f2, f3;
        int w;
        w = v.x;
        f0.x = (float)((w << 24) >> 24); f0.y = (float)((w << 16) >> 24);
        f0.z = (float)((w <<  8) >> 24); f0.w = (float)( w        >> 24);
        w = v.y;
        f1.x = (float)((w << 24) >> 24); f1.y = (float)((w << 16) >> 24);
        f1.z = (float)((w <<  8) >> 24); f1.w = (float)( w        >> 24);
        w = v.z;
        f2.x = (float)((w << 24) >> 24); f2.y = (float)((w << 16) >> 24);
        f2.z = (float)((w <<  8) >> 24); f2.w = (float)( w        >> 24);
        w = v.w;
        f3.x = (float)((w << 24) >> 24); f3.y = (float)((w << 16) >> 24);
        f3.z = (float)((w <<  8) >> 24); f3.w = (float)( w        >> 24);
        float4* d4 = reinterpret_cast<float4*>(dst);   // (OUT_HIST + g) % 4 == 0
        d4[0] = f0; d4[1] = f1; d4[2] = f2; d4[3] = f3;
    } else {
        // ---- rare scalar path: batch boundary or overwritten row ----
        #pragma unroll
        for (int j = 0; j < 16; j++) {
            unsigned int gg = g + j;
            unsigned int b  = gg / (unsigned)BSTRIDE;
            unsigned int off = gg - b * (unsigned)BSTRIDE;
            int mvb = move_count[b];
            int vb  = (mvb < MAX_MOVES);
            int mc  = mvb < 0 ? 0 : (mvb > MAX_MOVES - 1 ? MAX_MOVES - 1 : mvb);
            unsigned int rl = (unsigned)mc * HW;
            float val;
            if (vb && off >= rl && off < rl + HW) {
                unsigned int p = off - rl;
                val = board_state_val(board[b * HW + p]);
            } else {
                val = (float)hist[gg];
            }
            dst[j] = val;
        }
    }
}

// ---------------------------------------------------------------------------
// Kernel B: per-batch game logic (tiny): placement, captures, ko, pass, etc.
// One block per batch, 384 threads (361 board points + lane for scalars).
// ---------------------------------------------------------------------------
__global__ void __launch_bounds__(384)
board_update_kernel(const float* __restrict__ board,
                    const int* __restrict__ current_player,
                    const int* __restrict__ ko_points,
                    const int* __restrict__ pass_count,
                    const int* __restrict__ move_count,
                    const int* __restrict__ positions,
                    const int* __restrict__ roots,
                    const int* __restrict__ colour,
                    const int* __restrict__ cap_groups,
                    const int* __restrict__ cap_sizes,
                    const int* __restrict__ total_caps,
                    float* __restrict__ out)
{
    int b = blockIdx.x;
    int p = threadIdx.x;

    int p0 = positions[2 * b];
    int p1 = positions[2 * b + 1];
    bool is_pass = (p0 < 0) || (p1 < 0);
    bool play = !is_pass;
    int r = min(max(p0, 0), BH - 1);
    int c = min(max(p1, 0), BW - 1);
    int cp = current_player[b];
    int opp = 1 - cp;
    int flat = r * BW + c;

    int cgbase = ((b * BH + r) * BW + c) * 4;
    int nr0 = cap_groups[cgbase + 0];
    int nr1 = cap_groups[cgbase + 1];
    int nr2 = cap_groups[cgbase + 2];
    int nr3 = cap_groups[cgbase + 3];

    if (p < HW) {
        float bf = board[b * HW + p];
        float placed = (play && p == flat) ? (float)cp : bf;
        int rt = roots[b * HW + p];
        int col = colour[b * HW + p];
        bool cap = play && (col == opp) &&
                   ((nr0 >= 0 && rt == nr0) || (nr1 >= 0 && rt == nr1) ||
                    (nr2 >= 0 && rt == nr2) || (nr3 >= 0 && rt == nr3));
        out[OUT_BOARD + b * HW + p] = cap ? -1.0f : placed;
    }

    if (p == 0) {
        // ko point from single-stone capture
        int tc = total_caps[(b * BH + r) * BW + c];
        bool single_cap = (tc == 1) && play;
        int s0 = cap_sizes[cgbase + 0];
        int s1 = cap_sizes[cgbase + 1];
        int s2 = cap_sizes[cgbase + 2];
        int s3 = cap_sizes[cgbase + 3];
        int dir = (s0 == 1) ? 0 : (s1 == 1) ? 1 : (s2 == 1) ? 2 : (s3 == 1) ? 3 : 0;
        const int offs[4] = { -BW, BW, -1, 1 };
        int nbr = flat + offs[dir];
        // Python floor-division semantics for negative nbr
        int r_ko = (nbr >= 0) ? (nbr / BW) : -((-nbr + BW - 1) / BW);
        int c_ko = nbr - r_ko * BW;

        int ko_r, ko_c;
        if (play) {
            ko_r = single_cap ? r_ko : -1;
            ko_c = single_cap ? c_ko : -1;
        } else {
            ko_r = ko_points[2 * b];
            ko_c = ko_points[2 * b + 1];
        }
        out[OUT_KO + 2 * b]     = (float)ko_r;
        out[OUT_KO + 2 * b + 1] = (float)ko_c;
        out[OUT_PASS + b]   = (float)(is_pass ? pass_count[b] + 1 : 0);
        out[OUT_MV + b]     = (float)(move_count[b] + 1);
        out[OUT_PLAYER + b] = (float)(cp ^ 1);
    }
}

extern "C" void kernel_launch(void* const* d_in, const int* in_sizes, int n_in,
                              void* d_out, int out_size)
{
    const float*  board          = (const float*) d_in[0];
    const int*    current_player = (const int*)   d_in[1];
    const int*    ko_points      = (const int*)   d_in[2];
    const int*    pass_count     = (const int*)   d_in[3];
    const int8_t* board_history  = (const int8_t*)d_in[4];
    const int*    move_count     = (const int*)   d_in[5];
    const int*    positions      = (const int*)   d_in[6];
    const int*    roots          = (const int*)   d_in[7];
    const int*    colour         = (const int*)   d_in[8];
    const int*    cap_groups     = (const int*)   d_in[9];
    const int*    cap_sizes      = (const int*)   d_in[10];
    const int*    total_caps     = (const int*)   d_in[11];
    float* out = (float*)d_out;

    unsigned int blocks = (NCHUNK + 255u) / 256u;
    hist_copy_kernel<<<blocks, 256>>>(board_history, board, move_count, out);
    board_update_kernel<<<BATCH, 384>>>(board, current_player, ko_points, pass_count,
                                        move_count, positions, roots, colour,
                                        cap_groups, cap_sizes, total_caps, out);
}